// round 13
// baseline (speedup 1.0000x reference)
#include <cuda_runtime.h>
#include <cuda_bf16.h>
#include <math.h>

#define BATCH 65536
#define NPAIR 32768
#define DIM   256
#define NUSER 200000
#define NITEM 100000
#define FULLM 0xffffffffu

#define PROJ_SMEM (16 * 512 * 4)     // transposed att_w1 (staging only)
#define SWP_HALFS  (8 * 3 * 256)
#define MAIN_SMEM (SWP_HALFS * 2)    // 12288 B

typedef unsigned long long u64;

// persistent scratch (static device arrays: sanctioned no-alloc path)
__device__ float g_mproj[(size_t)NUSER * 16];
__device__ float g_iproj[(size_t)NITEM * 16];
__device__ unsigned char g_umark[NUSER];
__device__ unsigned char g_imark[NITEM];

// ---- packed f32x2 (FFMA2) helpers ----
__device__ __forceinline__ u64 ffma2(u64 a, u64 b, u64 c) {
    u64 d; asm("fma.rn.f32x2 %0,%1,%2,%3;" : "=l"(d) : "l"(a), "l"(b), "l"(c)); return d;
}
__device__ __forceinline__ u64 fadd2(u64 a, u64 b) {
    u64 d; asm("add.rn.f32x2 %0,%1,%2;" : "=l"(d) : "l"(a), "l"(b)); return d;
}
__device__ __forceinline__ u64 fmul2(u64 a, u64 b) {
    u64 d; asm("mul.rn.f32x2 %0,%1,%2;" : "=l"(d) : "l"(a), "l"(b)); return d;
}
__device__ __forceinline__ u64 dup2(float x) {
    u64 r; asm("mov.b64 %0,{%1,%1};" : "=l"(r) : "f"(x)); return r;
}
__device__ __forceinline__ float hadd2(u64 p) {
    float x, y; asm("mov.b64 {%0,%1},%2;" : "=f"(x), "=f"(y) : "l"(p));
    return x + y;
}
__device__ __forceinline__ u64 bf2f2(unsigned int u) {
    unsigned int lo = u << 16, hi = u & 0xffff0000u;
    u64 r; asm("mov.b64 %0,{%1,%2};" : "=l"(r) : "r"(lo), "r"(hi)); return r;
}
__device__ __forceinline__ void pfl2(const void* p) {
    asm volatile("prefetch.global.L2 [%0];" :: "l"(p));
}

// SEL-free folds (slot i holds value i ^ (lane&mask))
__device__ __forceinline__ float fold16x(float* A) {
    #pragma unroll
    for (int d = 8; d >= 1; d >>= 1)
        #pragma unroll
        for (int i = 0; i < d; i++)
            A[i] += __shfl_xor_sync(FULLM, A[i + d], d);
    float v = A[0];
    v += __shfl_xor_sync(FULLM, v, 16);
    return v;
}
__device__ __forceinline__ float fold8x(float* A) {
    #pragma unroll
    for (int d = 4; d >= 1; d >>= 1)
        #pragma unroll
        for (int i = 0; i < d; i++)
            A[i] += __shfl_xor_sync(FULLM, A[i + d], d);
    float v = A[0];
    v += __shfl_xor_sync(FULLM, v, 8);
    v += __shfl_xor_sync(FULLM, v, 16);
    return v;
}

__device__ __forceinline__ void perm4i(const int* in, int* out, int p) {
    int t0 = (p & 1) ? in[1] : in[0];
    int t1 = (p & 1) ? in[0] : in[1];
    int t2 = (p & 1) ? in[3] : in[2];
    int t3 = (p & 1) ? in[2] : in[3];
    out[0] = (p & 2) ? t2 : t0;
    out[1] = (p & 2) ? t3 : t1;
    out[2] = (p & 2) ? t0 : t2;
    out[3] = (p & 2) ? t1 : t3;
}

// ============================================================================
// Kernel 0: mark referenced rows (input-deterministic; persistence is benign)
// ============================================================================
__global__ __launch_bounds__(256)
void mark_kernel(const int* __restrict__ group_inputs,
                 const int* __restrict__ item_inputs,
                 const int* __restrict__ group_members)
{
    int t = blockIdx.x * 256 + threadIdx.x;
    if (t >= BATCH) return;
    g_imark[item_inputs[t]] = 1;
    const int4 m = *(const int4*)(group_members + group_inputs[t] * 4);
    g_umark[m.x] = 1;
    g_umark[m.y] = 1;
    g_umark[m.z] = 1;
    g_umark[m.w] = 1;
}

// ============================================================================
// Kernel 1: attention projections with register-resident weights.
//   Phase U: mproj[u][f] = <user_emb[u], att_w1[0:256, f]>  (marked users only)
//   Phase I: iproj[i][f] = <item_emb[i], att_w1[256:512, f]> (marked items only)
// Lane owns dims {4l..4l+3, 128+4l..+3}; weight slot i holds f = i ^ (lane&15).
// Steady-state loop has ZERO shared-memory traffic.
// ============================================================================
__global__ __launch_bounds__(128)
void proj_kernel(const float* __restrict__ user_emb,
                 const float* __restrict__ item_emb,
                 const float* __restrict__ att_w1)
{
    extern __shared__ float sw[];
    for (int i = threadIdx.x; i < 512 * 16; i += blockDim.x) {
        int d = i >> 4, f = i & 15;
        sw[f * 512 + d] = att_w1[i];   // transposed: sw[f*512 + d]
    }
    __syncthreads();

    const int lane = threadIdx.x & 31;
    const int gw   = blockIdx.x * 4 + (threadIdx.x >> 5);
    const int nw   = gridDim.x * 4;
    const int l15  = lane & 15;

    #pragma unroll
    for (int phase = 0; phase < 2; phase++) {
        const int wbase = phase ? 256 : 0;
        const int ntask = phase ? (NITEM / 2) : (NUSER / 2);
        const float* src = phase ? item_emb : user_emb;
        float* dst = phase ? g_iproj : g_mproj;
        const unsigned char* mark = phase ? g_imark : g_umark;

        // load this phase's weights into registers, slot-ordered (static indices)
        u64 wr[16][4];
        #pragma unroll
        for (int i = 0; i < 16; i++) {
            const float* base = sw + (((i ^ l15)) << 9) + wbase + 4 * lane;
            ulonglong2 a = *(const ulonglong2*)(base);
            ulonglong2 b = *(const ulonglong2*)(base + 128);
            wr[i][0] = a.x; wr[i][1] = a.y; wr[i][2] = b.x; wr[i][3] = b.y;
        }

        u64 r0d[4] = {0, 0, 0, 0};
        u64 r1d[4] = {0, 0, 0, 0};

        for (int t = gw; t < ntask; t += nw) {
            const int r0 = 2 * t;
            const unsigned char f0 = mark[r0];
            const unsigned char f1 = mark[r0 + 1];
            if (!(f0 | f1)) continue;

            if (f0) {
                const ulonglong2* p0 = (const ulonglong2*)(src + (size_t)r0 * DIM);
                ulonglong2 a0 = p0[lane], a1 = p0[32 + lane];
                r0d[0] = a0.x; r0d[1] = a0.y; r0d[2] = a1.x; r0d[3] = a1.y;
            }
            if (f1) {
                const ulonglong2* p1 = (const ulonglong2*)(src + (size_t)(r0 + 1) * DIM);
                ulonglong2 b0 = p1[lane], b1 = p1[32 + lane];
                r1d[0] = b0.x; r1d[1] = b0.y; r1d[2] = b1.x; r1d[3] = b1.y;
            }

            float A0[16], A1[16];
            #pragma unroll
            for (int j = 0; j < 16; j++) {
                u64 c0 = fmul2(r0d[0], wr[j][0]);
                c0 = ffma2(r0d[1], wr[j][1], c0);
                c0 = ffma2(r0d[2], wr[j][2], c0);
                c0 = ffma2(r0d[3], wr[j][3], c0);
                A0[j] = hadd2(c0);
                u64 c1 = fmul2(r1d[0], wr[j][0]);
                c1 = ffma2(r1d[1], wr[j][1], c1);
                c1 = ffma2(r1d[2], wr[j][2], c1);
                c1 = ffma2(r1d[3], wr[j][3], c1);
                A1[j] = hadd2(c1);
            }
            float v0 = fold16x(A0);   // lane holds f = lane&15 of row r0
            float v1 = fold16x(A1);
            if (f0 && lane < 16)  dst[(size_t)r0 * 16 + lane] = v0;
            if (f1 && lane >= 16) dst[(size_t)(r0 + 1) * 16 + (lane - 16)] = v1;
        }
    }
}

// ============================================================================
// Kernel 2: main — attention via projection lookups (unchanged from R11/12)
// ============================================================================
__global__ __launch_bounds__(128, 4)
void agree_kernel(
    const int*   __restrict__ group_inputs,
    const int*   __restrict__ item_inputs,
    const int*   __restrict__ group_members,
    const float* __restrict__ user_emb,
    const float* __restrict__ item_emb,
    const float* __restrict__ group_emb,
    const float* __restrict__ att_b1,
    const float* __restrict__ att_w2,
    const float* __restrict__ att_b2,
    const float* __restrict__ cls_w,
    const float* __restrict__ cls_b,
    const float* __restrict__ pred_w1,
    const float* __restrict__ pred_b1,
    const float* __restrict__ pred_w2,
    const float* __restrict__ pred_b2,
    float*       __restrict__ out)
{
    extern __shared__ float sm[];
    __nv_bfloat16* swp = (__nv_bfloat16*)sm;

    const int tid = threadIdx.x;
    for (int i = tid; i < SWP_HALFS; i += blockDim.x) {
        int k   = i / 768;
        int rem = i - k * 768;
        int r   = rem >> 8;
        int qq  = rem & 255;
        int ln  = qq >> 3;
        int ii  = qq & 7;
        int j   = r * 256 + ((ii & 4) ? 128 : 0) + 4 * ln + (ii & 3);
        swp[i] = __float2bfloat16(pred_w1[j * 8 + k]);
    }
    __syncthreads();

    const int lane  = tid & 31;
    const int gwarp = blockIdx.x * 4 + (tid >> 5);
    const int nwarp = gridDim.x * 4;

    const int e_l = lane >> 4;
    const int f_l = lane & 15;
    const int l3  = lane & 3;
    const int l7  = lane & 7;

    const float b1f  = __ldg(att_b1 + f_l);
    const float w2f  = __ldg(att_w2 + f_l);
    const float b2v  = __ldg(att_b2);
    const float pbk  = __ldg(pred_b1 + l7);
    const float pwk  = __ldg(pred_w2 + l7);
    const float clw0 = __ldg(cls_w), clw1 = __ldg(cls_w + 1);
    const float clb0 = __ldg(cls_b), clb1 = __ldg(cls_b + 1);
    const float pb2  = __ldg(pred_b2);

    int gidA = group_inputs[2 * gwarp];
    int gidB = group_inputs[2 * gwarp + 1];
    int iidA = item_inputs[2 * gwarp];
    int iidB = item_inputs[2 * gwarp + 1];
    int4 mA = *(const int4*)(group_members + gidA * 4);
    int4 mB = *(const int4*)(group_members + gidB * 4);

    for (int pp = gwarp; pp < NPAIR; pp += nwarp) {
        // attention projection gathers
        float mp[4], ip;
        {
            int rawE[4];
            rawE[0] = e_l ? mB.x : mA.x;
            rawE[1] = e_l ? mB.y : mA.y;
            rawE[2] = e_l ? mB.z : mA.z;
            rawE[3] = e_l ? mB.w : mA.w;
            int mide[4];
            perm4i(rawE, mide, l3);
            #pragma unroll
            for (int i = 0; i < 4; i++)
                mp[i] = __ldg(g_mproj + (size_t)mide[i] * 16 + f_l);
            const int iidE = e_l ? iidB : iidA;
            ip = __ldg(g_iproj + (size_t)iidE * 16 + f_l);
        }

        // row gathers
        u64 pmem[2][4][4], pit[2][4];
        {
            int mAr[4] = {mA.x, mA.y, mA.z, mA.w};
            int mBr[4] = {mB.x, mB.y, mB.z, mB.w};
            #pragma unroll
            for (int s = 0; s < 4; s++) {
                const ulonglong2* rA = (const ulonglong2*)(user_emb + (size_t)mAr[s] * DIM);
                const ulonglong2* rB = (const ulonglong2*)(user_emb + (size_t)mBr[s] * DIM);
                ulonglong2 a0 = rA[lane], a1 = rA[32 + lane];
                ulonglong2 c0 = rB[lane], c1 = rB[32 + lane];
                pmem[0][s][0] = a0.x; pmem[0][s][1] = a0.y; pmem[0][s][2] = a1.x; pmem[0][s][3] = a1.y;
                pmem[1][s][0] = c0.x; pmem[1][s][1] = c0.y; pmem[1][s][2] = c1.x; pmem[1][s][3] = c1.y;
            }
            const ulonglong2* iA = (const ulonglong2*)(item_emb + (size_t)iidA * DIM);
            const ulonglong2* iB = (const ulonglong2*)(item_emb + (size_t)iidB * DIM);
            ulonglong2 a0 = iA[lane], a1 = iA[32 + lane];
            ulonglong2 c0 = iB[lane], c1 = iB[32 + lane];
            pit[0][0] = a0.x; pit[0][1] = a0.y; pit[0][2] = a1.x; pit[0][3] = a1.y;
            pit[1][0] = c0.x; pit[1][1] = c0.y; pit[1][2] = c1.x; pit[1][3] = c1.y;
        }

        // early-issue next iteration's index chain
        const int ppn = pp + nwarp;
        const bool hn = ppn < NPAIR;
        const int bn = hn ? 2 * ppn : 2 * pp;
        int gidAn = group_inputs[bn];
        int gidBn = group_inputs[bn + 1];
        int iidAn = item_inputs[bn];
        int iidBn = item_inputs[bn + 1];
        int4 mAn = *(const int4*)(group_members + gidAn * 4);
        int4 mBn = *(const int4*)(group_members + gidBn * 4);

        // logits from projections
        float lv;
        {
            float A[4];
            #pragma unroll
            for (int i = 0; i < 4; i++)
                A[i] = fmaxf(mp[i] + ip + b1f, 0.f) * w2f;
            #pragma unroll
            for (int d = 2; d >= 1; d >>= 1)
                #pragma unroll
                for (int i = 0; i < d; i++)
                    A[i] += __shfl_xor_sync(FULLM, A[i + d], d);
            lv = A[0];
            lv += __shfl_xor_sync(FULLM, lv, 4);
            lv += __shfl_xor_sync(FULLM, lv, 8);
        }

        // prefetch next iteration's rows + projections
        if (hn) {
            int mn[8] = {mAn.x, mAn.y, mAn.z, mAn.w, mBn.x, mBn.y, mBn.z, mBn.w};
            #pragma unroll
            for (int s = 0; s < 8; s++) {
                const float* r = user_emb + (size_t)mn[s] * DIM + 4 * lane;
                pfl2(r); pfl2(r + 128);
                pfl2(g_mproj + (size_t)mn[s] * 16);
            }
            const float* ra = item_emb + (size_t)iidAn * DIM + 4 * lane;
            const float* rb = item_emb + (size_t)iidBn * DIM + 4 * lane;
            pfl2(ra); pfl2(ra + 128);
            pfl2(rb); pfl2(rb + 128);
            pfl2(g_iproj + (size_t)iidAn * 16);
            pfl2(g_iproj + (size_t)iidBn * 16);
            const float* ga = group_emb + (size_t)gidAn * DIM + 4 * lane;
            const float* gb = group_emb + (size_t)gidBn * DIM + 4 * lane;
            pfl2(ga); pfl2(ga + 128);
            pfl2(gb); pfl2(gb + 128);
        }

        // softmax / argmax / classifier
        float wt[2][4];
        int   pc[2];
        float cw[2][4];
        #pragma unroll
        for (int e = 0; e < 2; e++) {
            float logit[4];
            #pragma unroll
            for (int s = 0; s < 4; s++)
                logit[s] = __shfl_sync(FULLM, lv, e * 16 + s) + b2v;

            float mx = logit[0]; int ix = 0;
            #pragma unroll
            for (int s = 1; s < 4; s++)
                if (logit[s] > mx) { mx = logit[s]; ix = s; }

            float ev[4], sum = 0.f;
            #pragma unroll
            for (int s = 0; s < 4; s++) { ev[s] = __expf(logit[s] - mx); sum += ev[s]; }
            float inv = 1.f / sum;
            #pragma unroll
            for (int s = 0; s < 4; s++) wt[e][s] = ev[s] * inv;

            float s0 = inv * clw0 + clb0;
            float s1 = inv * clw1 + clb1;
            pc[e] = (s1 > s0) ? 1 : 0;
            #pragma unroll
            for (int s = 0; s < 4; s++)
                cw[e][s] = pc[e] ? ((s == ix) ? 1.f : 0.f) : wt[e][s];
        }

        // epilogue
        u64 pgv[2][4], pel[2][4];
        {
            const ulonglong2* gA = (const ulonglong2*)(group_emb + (size_t)gidA * DIM);
            const ulonglong2* gB = (const ulonglong2*)(group_emb + (size_t)gidB * DIM);
            #pragma unroll
            for (int e = 0; e < 2; e++) {
                u64 c0 = dup2(cw[e][0]), c1 = dup2(cw[e][1]);
                u64 c2 = dup2(cw[e][2]), c3 = dup2(cw[e][3]);
                const ulonglong2* grow = (e == 0) ? gA : gB;
                ulonglong2 g0 = grow[lane], g1 = grow[32 + lane];
                u64 grp[4] = {g0.x, g0.y, g1.x, g1.y};
                #pragma unroll
                for (int j = 0; j < 4; j++) {
                    u64 t = fmul2(pmem[e][0][j], c0);
                    t = ffma2(pmem[e][1][j], c1, t);
                    t = ffma2(pmem[e][2][j], c2, t);
                    t = ffma2(pmem[e][3][j], c3, t);
                    t = fadd2(t, grp[j]);
                    pgv[e][j] = t;
                    pel[e][j] = fmul2(t, pit[e][j]);
                }
            }
        }

        // prediction MLP
        float A20[8], A21[8];
        #pragma unroll
        for (int k = 0; k < 8; k++) {
            const int kk = k ^ l7;
            u64 a0 = 0ull, a1 = 0ull;
            #pragma unroll
            for (int r = 0; r < 3; r++) {
                const u64* v0 = (r == 0) ? pel[0] : (r == 1) ? pgv[0] : pit[0];
                const u64* v1 = (r == 0) ? pel[1] : (r == 1) ? pgv[1] : pit[1];
                uint4 u = *(const uint4*)(swp + (kk * 3 + r) * 256 + lane * 8);
                u64 w0 = bf2f2(u.x), w1 = bf2f2(u.y), w2 = bf2f2(u.z), w3 = bf2f2(u.w);
                a0 = ffma2(v0[0], w0, a0);
                a0 = ffma2(v0[1], w1, a0);
                a0 = ffma2(v0[2], w2, a0);
                a0 = ffma2(v0[3], w3, a0);
                a1 = ffma2(v1[0], w0, a1);
                a1 = ffma2(v1[1], w1, a1);
                a1 = ffma2(v1[2], w2, a1);
                a1 = ffma2(v1[3], w3, a1);
            }
            A20[k] = hadd2(a0);
            A21[k] = hadd2(a1);
        }

        float y[2];
        #pragma unroll
        for (int e = 0; e < 2; e++) {
            float v = fold8x(e == 0 ? A20 : A21);
            float hz = fmaxf(v + pbk, 0.f) * pwk;
            hz += __shfl_xor_sync(FULLM, hz, 1);
            hz += __shfl_xor_sync(FULLM, hz, 2);
            hz += __shfl_xor_sync(FULLM, hz, 4);
            y[e] = 1.f / (1.f + __expf(-(hz + pb2)));
        }

        if (lane < 2) {
            const int e = lane;
            const int b = 2 * pp + e;
            out[b] = y[e];
            *(float4*)(out + BATCH + 4 * b) = make_float4(wt[e][0], wt[e][1], wt[e][2], wt[e][3]);
            out[5 * BATCH + b] = (float)pc[e];
        }

        gidA = gidAn; gidB = gidBn; iidA = iidAn; iidB = iidBn;
        mA = mAn; mB = mBn;
    }
}

extern "C" void kernel_launch(void* const* d_in, const int* in_sizes, int n_in,
                              void* d_out, int out_size)
{
    (void)in_sizes; (void)n_in; (void)out_size;
    cudaFuncSetAttribute(proj_kernel,
                         cudaFuncAttributeMaxDynamicSharedMemorySize, PROJ_SMEM);
    cudaFuncSetAttribute(agree_kernel,
                         cudaFuncAttributeMaxDynamicSharedMemorySize, MAIN_SMEM);

    mark_kernel<<<(BATCH + 255) / 256, 256>>>(
        (const int*)d_in[0], (const int*)d_in[1], (const int*)d_in[2]);

    proj_kernel<<<592, 128, PROJ_SMEM>>>(
        (const float*)d_in[3],   // user_emb
        (const float*)d_in[4],   // item_emb
        (const float*)d_in[6]);  // att_w1

    agree_kernel<<<592, 128, MAIN_SMEM>>>(
        (const int*)d_in[0],  (const int*)d_in[1],  (const int*)d_in[2],
        (const float*)d_in[3], (const float*)d_in[4], (const float*)d_in[5],
        (const float*)d_in[7],   // att_b1
        (const float*)d_in[8],   // att_w2
        (const float*)d_in[9],   // att_b2
        (const float*)d_in[10],  // cls_w
        (const float*)d_in[11],  // cls_b
        (const float*)d_in[12],  // pred_w1
        (const float*)d_in[13],  // pred_b1
        (const float*)d_in[14],  // pred_w2
        (const float*)d_in[15],  // pred_b2
        (float*)d_out);
}

// round 15
// speedup vs baseline: 1.4221x; 1.4221x over previous
#include <cuda_runtime.h>
#include <cuda_bf16.h>
#include <math.h>

#define BATCH 65536
#define NPAIR 32768
#define DIM   256
#define NUSER 200000
#define NITEM 100000
#define FULLM 0xffffffffu

#define PROJ_SMEM (16 * 512 * 4)     // transposed att_w1
#define SWP_HALFS  (8 * 3 * 256)
#define MAIN_SMEM (SWP_HALFS * 2)    // 12288 B

typedef unsigned long long u64;

// persistent scratch (static device arrays: sanctioned no-alloc path)
__device__ float g_mproj[(size_t)NUSER * 16];
__device__ float g_iproj[(size_t)NITEM * 16];
__device__ int g_uflag[NUSER];
__device__ int g_iflag[NITEM];
__device__ int g_ulist[NUSER];
__device__ int g_ilist[NITEM];
__device__ int g_cnt[2];             // [0]=users, [1]=items

// ---- packed f32x2 (FFMA2) helpers ----
__device__ __forceinline__ u64 ffma2(u64 a, u64 b, u64 c) {
    u64 d; asm("fma.rn.f32x2 %0,%1,%2,%3;" : "=l"(d) : "l"(a), "l"(b), "l"(c)); return d;
}
__device__ __forceinline__ u64 fadd2(u64 a, u64 b) {
    u64 d; asm("add.rn.f32x2 %0,%1,%2;" : "=l"(d) : "l"(a), "l"(b)); return d;
}
__device__ __forceinline__ u64 fmul2(u64 a, u64 b) {
    u64 d; asm("mul.rn.f32x2 %0,%1,%2;" : "=l"(d) : "l"(a), "l"(b)); return d;
}
__device__ __forceinline__ u64 dup2(float x) {
    u64 r; asm("mov.b64 %0,{%1,%1};" : "=l"(r) : "f"(x)); return r;
}
__device__ __forceinline__ float hadd2(u64 p) {
    float x, y; asm("mov.b64 {%0,%1},%2;" : "=f"(x), "=f"(y) : "l"(p));
    return x + y;
}
__device__ __forceinline__ u64 bf2f2(unsigned int u) {
    unsigned int lo = u << 16, hi = u & 0xffff0000u;
    u64 r; asm("mov.b64 %0,{%1,%2};" : "=l"(r) : "r"(lo), "r"(hi)); return r;
}
__device__ __forceinline__ void pfl2(const void* p) {
    asm volatile("prefetch.global.L2 [%0];" :: "l"(p));
}

// SEL-free fold over 8 values: slot i holds partial of value (i ^ (lane&7));
// every lane returns the full 32-lane sum of value (lane&7).
__device__ __forceinline__ float fold8x(float* A) {
    #pragma unroll
    for (int d = 4; d >= 1; d >>= 1)
        #pragma unroll
        for (int i = 0; i < d; i++)
            A[i] += __shfl_xor_sync(FULLM, A[i + d], d);
    float v = A[0];
    v += __shfl_xor_sync(FULLM, v, 8);
    v += __shfl_xor_sync(FULLM, v, 16);
    return v;
}

__device__ __forceinline__ void perm4i(const int* in, int* out, int p) {
    int t0 = (p & 1) ? in[1] : in[0];
    int t1 = (p & 1) ? in[0] : in[1];
    int t2 = (p & 1) ? in[3] : in[2];
    int t3 = (p & 1) ? in[2] : in[3];
    out[0] = (p & 2) ? t2 : t0;
    out[1] = (p & 2) ? t3 : t1;
    out[2] = (p & 2) ? t0 : t2;
    out[3] = (p & 2) ? t1 : t3;
}

// ============================================================================
// Kernel -1: zero flags + counters (every launch: identical work, no caching)
// ============================================================================
__global__ __launch_bounds__(256)
void zero_kernel()
{
    const int nt = gridDim.x * 256;
    for (int i = blockIdx.x * 256 + threadIdx.x; i < NUSER; i += nt) g_uflag[i] = 0;
    for (int i = blockIdx.x * 256 + threadIdx.x; i < NITEM; i += nt) g_iflag[i] = 0;
    if (blockIdx.x == 0 && threadIdx.x < 2) g_cnt[threadIdx.x] = 0;
}

// ============================================================================
// Kernel 0: mark + compact — build dense lists of unique referenced rows
// ============================================================================
__global__ __launch_bounds__(256)
void mark_kernel(const int* __restrict__ group_inputs,
                 const int* __restrict__ item_inputs,
                 const int* __restrict__ group_members)
{
    int t = blockIdx.x * 256 + threadIdx.x;
    if (t >= BATCH) return;
    const int it = item_inputs[t];
    if (atomicExch(&g_iflag[it], 1) == 0) {
        int p = atomicAdd(&g_cnt[1], 1);
        g_ilist[p] = it;
    }
    const int4 m = *(const int4*)(group_members + group_inputs[t] * 4);
    int u[4] = {m.x, m.y, m.z, m.w};
    #pragma unroll
    for (int s = 0; s < 4; s++) {
        if (atomicExch(&g_uflag[u[s]], 1) == 0) {
            int p = atomicAdd(&g_cnt[0], 1);
            g_ulist[p] = u[s];
        }
    }
}

// ============================================================================
// Kernel 1: projections over DENSE lists, 4 rows/task, weights in smem.
//   users: mproj[u][f] = <user_emb[u], att_w1[0:256, f]>
//   items: iproj[i][f] = <item_emb[i], att_w1[256:512, f]>
// Lane owns dims {4l..4l+3, 128+4l..+3}; f chunked by 8 with XOR slot perm.
// ============================================================================
__global__ __launch_bounds__(128, 4)
void proj_kernel(const float* __restrict__ user_emb,
                 const float* __restrict__ item_emb,
                 const float* __restrict__ att_w1)
{
    extern __shared__ float sw[];
    for (int i = threadIdx.x; i < 512 * 16; i += blockDim.x) {
        int d = i >> 4, f = i & 15;
        sw[f * 512 + d] = att_w1[i];   // transposed: sw[f*512 + d]
    }
    __syncthreads();

    const int lane = threadIdx.x & 31;
    const int gw   = blockIdx.x * 4 + (threadIdx.x >> 5);
    const int nw   = gridDim.x * 4;
    const int l7   = lane & 7;
    const int g    = lane >> 3;        // row within task this lane stores

    const int ucnt  = g_cnt[0];
    const int icnt  = g_cnt[1];
    const int utask = (ucnt + 3) >> 2;
    const int itask = (icnt + 3) >> 2;
    const int ttask = utask + itask;

    for (int t = gw; t < ttask; t += nw) {
        const bool isU = t < utask;
        const int* list = isU ? g_ulist : g_ilist;
        const int  cnt  = isU ? ucnt : icnt;
        const int  base = (isU ? t : t - utask) * 4;
        const float* src = isU ? user_emb : item_emb;
        float* dst = isU ? g_mproj : g_iproj;
        const int wbase = isU ? 0 : 256;

        // list ids (dense; tail guarded)
        int4 l4 = *(const int4*)(list + base);
        bool val[4];
        int  rid[4];
        val[0] = true;                 rid[0] = l4.x;
        val[1] = base + 1 < cnt;       rid[1] = val[1] ? l4.y : l4.x;
        val[2] = base + 2 < cnt;       rid[2] = val[2] ? l4.z : l4.x;
        val[3] = base + 3 < cnt;       rid[3] = val[3] ? l4.w : l4.x;

        // load 4 rows
        u64 rd[4][4];
        #pragma unroll
        for (int r = 0; r < 4; r++) {
            const ulonglong2* p = (const ulonglong2*)(src + (size_t)rid[r] * DIM);
            ulonglong2 a0 = p[lane], a1 = p[32 + lane];
            rd[r][0] = a0.x; rd[r][1] = a0.y; rd[r][2] = a1.x; rd[r][3] = a1.y;
        }

        // prefetch next task's rows (same phase only)
        {
            const int tn = t + nw;
            if (tn < ttask && (tn < utask) == isU) {
                const int nb = (isU ? tn : tn - utask) * 4;
                int4 n4 = *(const int4*)(list + nb);
                int nr[4] = {n4.x, n4.y, n4.z, n4.w};
                #pragma unroll
                for (int r = 0; r < 4; r++) {
                    const float* q = src + (size_t)nr[r] * DIM + 4 * lane;
                    pfl2(q); pfl2(q + 128);
                }
            }
        }

        // two f-chunks of 8
        #pragma unroll
        for (int c = 0; c < 2; c++) {
            float A0[8], A1[8], A2[8], A3[8];
            #pragma unroll
            for (int j = 0; j < 8; j++) {
                const float* w = sw + ((c * 8 + (j ^ l7)) << 9) + wbase + 4 * lane;
                ulonglong2 wa = *(const ulonglong2*)w;
                ulonglong2 wb = *(const ulonglong2*)(w + 128);
                u64 a = fmul2(rd[0][0], wa.x);
                a = ffma2(rd[0][1], wa.y, a);
                a = ffma2(rd[0][2], wb.x, a);
                a = ffma2(rd[0][3], wb.y, a);
                A0[j] = hadd2(a);
                u64 b = fmul2(rd[1][0], wa.x);
                b = ffma2(rd[1][1], wa.y, b);
                b = ffma2(rd[1][2], wb.x, b);
                b = ffma2(rd[1][3], wb.y, b);
                A1[j] = hadd2(b);
                u64 cc = fmul2(rd[2][0], wa.x);
                cc = ffma2(rd[2][1], wa.y, cc);
                cc = ffma2(rd[2][2], wb.x, cc);
                cc = ffma2(rd[2][3], wb.y, cc);
                A2[j] = hadd2(cc);
                u64 dd = fmul2(rd[3][0], wa.x);
                dd = ffma2(rd[3][1], wa.y, dd);
                dd = ffma2(rd[3][2], wb.x, dd);
                dd = ffma2(rd[3][3], wb.y, dd);
                A3[j] = hadd2(dd);
            }
            float v0 = fold8x(A0);
            float v1 = fold8x(A1);
            float v2 = fold8x(A2);
            float v3 = fold8x(A3);
            // lane stores row g, f = c*8 + l7
            float vg = (g & 2) ? ((g & 1) ? v3 : v2) : ((g & 1) ? v1 : v0);
            int  rg  = (g & 2) ? ((g & 1) ? rid[3] : rid[2]) : ((g & 1) ? rid[1] : rid[0]);
            bool ok  = (g & 2) ? ((g & 1) ? val[3] : val[2]) : ((g & 1) ? val[1] : val[0]);
            if (ok) dst[(size_t)rg * 16 + c * 8 + l7] = vg;
        }
    }
}

// ============================================================================
// Kernel 2: main — unchanged from R12/R13 (76 us, proven)
// ============================================================================
__global__ __launch_bounds__(128, 4)
void agree_kernel(
    const int*   __restrict__ group_inputs,
    const int*   __restrict__ item_inputs,
    const int*   __restrict__ group_members,
    const float* __restrict__ user_emb,
    const float* __restrict__ item_emb,
    const float* __restrict__ group_emb,
    const float* __restrict__ att_b1,
    const float* __restrict__ att_w2,
    const float* __restrict__ att_b2,
    const float* __restrict__ cls_w,
    const float* __restrict__ cls_b,
    const float* __restrict__ pred_w1,
    const float* __restrict__ pred_b1,
    const float* __restrict__ pred_w2,
    const float* __restrict__ pred_b2,
    float*       __restrict__ out)
{
    extern __shared__ float sm[];
    __nv_bfloat16* swp = (__nv_bfloat16*)sm;

    const int tid = threadIdx.x;
    for (int i = tid; i < SWP_HALFS; i += blockDim.x) {
        int k   = i / 768;
        int rem = i - k * 768;
        int r   = rem >> 8;
        int qq  = rem & 255;
        int ln  = qq >> 3;
        int ii  = qq & 7;
        int j   = r * 256 + ((ii & 4) ? 128 : 0) + 4 * ln + (ii & 3);
        swp[i] = __float2bfloat16(pred_w1[j * 8 + k]);
    }
    __syncthreads();

    const int lane  = tid & 31;
    const int gwarp = blockIdx.x * 4 + (tid >> 5);
    const int nwarp = gridDim.x * 4;

    const int e_l = lane >> 4;
    const int f_l = lane & 15;
    const int l3  = lane & 3;
    const int l7  = lane & 7;

    const float b1f  = __ldg(att_b1 + f_l);
    const float w2f  = __ldg(att_w2 + f_l);
    const float b2v  = __ldg(att_b2);
    const float pbk  = __ldg(pred_b1 + l7);
    const float pwk  = __ldg(pred_w2 + l7);
    const float clw0 = __ldg(cls_w), clw1 = __ldg(cls_w + 1);
    const float clb0 = __ldg(cls_b), clb1 = __ldg(cls_b + 1);
    const float pb2  = __ldg(pred_b2);

    int gidA = group_inputs[2 * gwarp];
    int gidB = group_inputs[2 * gwarp + 1];
    int iidA = item_inputs[2 * gwarp];
    int iidB = item_inputs[2 * gwarp + 1];
    int4 mA = *(const int4*)(group_members + gidA * 4);
    int4 mB = *(const int4*)(group_members + gidB * 4);

    for (int pp = gwarp; pp < NPAIR; pp += nwarp) {
        float mp[4], ip;
        {
            int rawE[4];
            rawE[0] = e_l ? mB.x : mA.x;
            rawE[1] = e_l ? mB.y : mA.y;
            rawE[2] = e_l ? mB.z : mA.z;
            rawE[3] = e_l ? mB.w : mA.w;
            int mide[4];
            perm4i(rawE, mide, l3);
            #pragma unroll
            for (int i = 0; i < 4; i++)
                mp[i] = __ldg(g_mproj + (size_t)mide[i] * 16 + f_l);
            const int iidE = e_l ? iidB : iidA;
            ip = __ldg(g_iproj + (size_t)iidE * 16 + f_l);
        }

        u64 pmem[2][4][4], pit[2][4];
        {
            int mAr[4] = {mA.x, mA.y, mA.z, mA.w};
            int mBr[4] = {mB.x, mB.y, mB.z, mB.w};
            #pragma unroll
            for (int s = 0; s < 4; s++) {
                const ulonglong2* rA = (const ulonglong2*)(user_emb + (size_t)mAr[s] * DIM);
                const ulonglong2* rB = (const ulonglong2*)(user_emb + (size_t)mBr[s] * DIM);
                ulonglong2 a0 = rA[lane], a1 = rA[32 + lane];
                ulonglong2 c0 = rB[lane], c1 = rB[32 + lane];
                pmem[0][s][0] = a0.x; pmem[0][s][1] = a0.y; pmem[0][s][2] = a1.x; pmem[0][s][3] = a1.y;
                pmem[1][s][0] = c0.x; pmem[1][s][1] = c0.y; pmem[1][s][2] = c1.x; pmem[1][s][3] = c1.y;
            }
            const ulonglong2* iA = (const ulonglong2*)(item_emb + (size_t)iidA * DIM);
            const ulonglong2* iB = (const ulonglong2*)(item_emb + (size_t)iidB * DIM);
            ulonglong2 a0 = iA[lane], a1 = iA[32 + lane];
            ulonglong2 c0 = iB[lane], c1 = iB[32 + lane];
            pit[0][0] = a0.x; pit[0][1] = a0.y; pit[0][2] = a1.x; pit[0][3] = a1.y;
            pit[1][0] = c0.x; pit[1][1] = c0.y; pit[1][2] = c1.x; pit[1][3] = c1.y;
        }

        const int ppn = pp + nwarp;
        const bool hn = ppn < NPAIR;
        const int bn = hn ? 2 * ppn : 2 * pp;
        int gidAn = group_inputs[bn];
        int gidBn = group_inputs[bn + 1];
        int iidAn = item_inputs[bn];
        int iidBn = item_inputs[bn + 1];
        int4 mAn = *(const int4*)(group_members + gidAn * 4);
        int4 mBn = *(const int4*)(group_members + gidBn * 4);

        float lv;
        {
            float A[4];
            #pragma unroll
            for (int i = 0; i < 4; i++)
                A[i] = fmaxf(mp[i] + ip + b1f, 0.f) * w2f;
            #pragma unroll
            for (int d = 2; d >= 1; d >>= 1)
                #pragma unroll
                for (int i = 0; i < d; i++)
                    A[i] += __shfl_xor_sync(FULLM, A[i + d], d);
            lv = A[0];
            lv += __shfl_xor_sync(FULLM, lv, 4);
            lv += __shfl_xor_sync(FULLM, lv, 8);
        }

        if (hn) {
            int mn[8] = {mAn.x, mAn.y, mAn.z, mAn.w, mBn.x, mBn.y, mBn.z, mBn.w};
            #pragma unroll
            for (int s = 0; s < 8; s++) {
                const float* r = user_emb + (size_t)mn[s] * DIM + 4 * lane;
                pfl2(r); pfl2(r + 128);
                pfl2(g_mproj + (size_t)mn[s] * 16);
            }
            const float* ra = item_emb + (size_t)iidAn * DIM + 4 * lane;
            const float* rb = item_emb + (size_t)iidBn * DIM + 4 * lane;
            pfl2(ra); pfl2(ra + 128);
            pfl2(rb); pfl2(rb + 128);
            pfl2(g_iproj + (size_t)iidAn * 16);
            pfl2(g_iproj + (size_t)iidBn * 16);
            const float* ga = group_emb + (size_t)gidAn * DIM + 4 * lane;
            const float* gb = group_emb + (size_t)gidBn * DIM + 4 * lane;
            pfl2(ga); pfl2(ga + 128);
            pfl2(gb); pfl2(gb + 128);
        }

        float wt[2][4];
        int   pc[2];
        float cw[2][4];
        #pragma unroll
        for (int e = 0; e < 2; e++) {
            float logit[4];
            #pragma unroll
            for (int s = 0; s < 4; s++)
                logit[s] = __shfl_sync(FULLM, lv, e * 16 + s) + b2v;

            float mx = logit[0]; int ix = 0;
            #pragma unroll
            for (int s = 1; s < 4; s++)
                if (logit[s] > mx) { mx = logit[s]; ix = s; }

            float ev[4], sum = 0.f;
            #pragma unroll
            for (int s = 0; s < 4; s++) { ev[s] = __expf(logit[s] - mx); sum += ev[s]; }
            float inv = 1.f / sum;
            #pragma unroll
            for (int s = 0; s < 4; s++) wt[e][s] = ev[s] * inv;

            float s0 = inv * clw0 + clb0;
            float s1 = inv * clw1 + clb1;
            pc[e] = (s1 > s0) ? 1 : 0;
            #pragma unroll
            for (int s = 0; s < 4; s++)
                cw[e][s] = pc[e] ? ((s == ix) ? 1.f : 0.f) : wt[e][s];
        }

        u64 pgv[2][4], pel[2][4];
        {
            const ulonglong2* gA = (const ulonglong2*)(group_emb + (size_t)gidA * DIM);
            const ulonglong2* gB = (const ulonglong2*)(group_emb + (size_t)gidB * DIM);
            #pragma unroll
            for (int e = 0; e < 2; e++) {
                u64 c0 = dup2(cw[e][0]), c1 = dup2(cw[e][1]);
                u64 c2 = dup2(cw[e][2]), c3 = dup2(cw[e][3]);
                const ulonglong2* grow = (e == 0) ? gA : gB;
                ulonglong2 g0 = grow[lane], g1 = grow[32 + lane];
                u64 grp[4] = {g0.x, g0.y, g1.x, g1.y};
                #pragma unroll
                for (int j = 0; j < 4; j++) {
                    u64 t = fmul2(pmem[e][0][j], c0);
                    t = ffma2(pmem[e][1][j], c1, t);
                    t = ffma2(pmem[e][2][j], c2, t);
                    t = ffma2(pmem[e][3][j], c3, t);
                    t = fadd2(t, grp[j]);
                    pgv[e][j] = t;
                    pel[e][j] = fmul2(t, pit[e][j]);
                }
            }
        }

        float A20[8], A21[8];
        #pragma unroll
        for (int k = 0; k < 8; k++) {
            const int kk = k ^ l7;
            u64 a0 = 0ull, a1 = 0ull;
            #pragma unroll
            for (int r = 0; r < 3; r++) {
                const u64* v0 = (r == 0) ? pel[0] : (r == 1) ? pgv[0] : pit[0];
                const u64* v1 = (r == 0) ? pel[1] : (r == 1) ? pgv[1] : pit[1];
                uint4 u = *(const uint4*)(swp + (kk * 3 + r) * 256 + lane * 8);
                u64 w0 = bf2f2(u.x), w1 = bf2f2(u.y), w2 = bf2f2(u.z), w3 = bf2f2(u.w);
                a0 = ffma2(v0[0], w0, a0);
                a0 = ffma2(v0[1], w1, a0);
                a0 = ffma2(v0[2], w2, a0);
                a0 = ffma2(v0[3], w3, a0);
                a1 = ffma2(v1[0], w0, a1);
                a1 = ffma2(v1[1], w1, a1);
                a1 = ffma2(v1[2], w2, a1);
                a1 = ffma2(v1[3], w3, a1);
            }
            A20[k] = hadd2(a0);
            A21[k] = hadd2(a1);
        }

        float y[2];
        #pragma unroll
        for (int e = 0; e < 2; e++) {
            float v = fold8x(e == 0 ? A20 : A21);
            float hz = fmaxf(v + pbk, 0.f) * pwk;
            hz += __shfl_xor_sync(FULLM, hz, 1);
            hz += __shfl_xor_sync(FULLM, hz, 2);
            hz += __shfl_xor_sync(FULLM, hz, 4);
            y[e] = 1.f / (1.f + __expf(-(hz + pb2)));
        }

        if (lane < 2) {
            const int e = lane;
            const int b = 2 * pp + e;
            out[b] = y[e];
            *(float4*)(out + BATCH + 4 * b) = make_float4(wt[e][0], wt[e][1], wt[e][2], wt[e][3]);
            out[5 * BATCH + b] = (float)pc[e];
        }

        gidA = gidAn; gidB = gidBn; iidA = iidAn; iidB = iidBn;
        mA = mAn; mB = mBn;
    }
}

extern "C" void kernel_launch(void* const* d_in, const int* in_sizes, int n_in,
                              void* d_out, int out_size)
{
    (void)in_sizes; (void)n_in; (void)out_size;
    cudaFuncSetAttribute(proj_kernel,
                         cudaFuncAttributeMaxDynamicSharedMemorySize, PROJ_SMEM);
    cudaFuncSetAttribute(agree_kernel,
                         cudaFuncAttributeMaxDynamicSharedMemorySize, MAIN_SMEM);

    zero_kernel<<<296, 256>>>();

    mark_kernel<<<(BATCH + 255) / 256, 256>>>(
        (const int*)d_in[0], (const int*)d_in[1], (const int*)d_in[2]);

    proj_kernel<<<592, 128, PROJ_SMEM>>>(
        (const float*)d_in[3],   // user_emb
        (const float*)d_in[4],   // item_emb
        (const float*)d_in[6]);  // att_w1

    agree_kernel<<<592, 128, MAIN_SMEM>>>(
        (const int*)d_in[0],  (const int*)d_in[1],  (const int*)d_in[2],
        (const float*)d_in[3], (const float*)d_in[4], (const float*)d_in[5],
        (const float*)d_in[7],   // att_b1
        (const float*)d_in[8],   // att_w2
        (const float*)d_in[9],   // att_b2
        (const float*)d_in[10],  // cls_w
        (const float*)d_in[11],  // cls_b
        (const float*)d_in[12],  // pred_w1
        (const float*)d_in[13],  // pred_b1
        (const float*)d_in[14],  // pred_w2
        (const float*)d_in[15],  // pred_b2
        (float*)d_out);
}